// round 2
// baseline (speedup 1.0000x reference)
#include <cuda_runtime.h>

#define DN 64   // EMB_DIM
#define AN 32   // N_ANCHORS
#define ET 96   // AN + DN combined K dimension

// Precomputed P' = (1/A) * set_emb @ W1  [32 x 64]
__device__ float g_P[AN * DN];

__global__ void precompute_P_kernel(const float* __restrict__ embeds,
                                    const float* __restrict__ W,
                                    const int*   __restrict__ anchorset_id) {
    int idx = blockIdx.x * blockDim.x + threadIdx.x;
    if (idx >= AN * DN) return;
    int a = idx >> 6;
    int d = idx & 63;
    long row = (long)anchorset_id[a];
    const float* erow = embeds + row * DN;
    float s = 0.0f;
#pragma unroll
    for (int e = 0; e < DN; e++) s = fmaf(erow[e], W[e * DN + d], s);
    g_P[idx] = s * (1.0f / (float)AN);
}

// Packed fp32x2 helpers
__device__ __forceinline__ unsigned long long pack2(float x) {
    unsigned long long r;
    asm("mov.b64 %0, {%1, %1};" : "=l"(r) : "f"(x));
    return r;
}
__device__ __forceinline__ void ffma2(unsigned long long& a,
                                      unsigned long long x,
                                      unsigned long long w) {
    asm("fma.rn.f32x2 %0, %1, %2, %0;" : "+l"(a) : "l"(x), "l"(w));
}
__device__ __forceinline__ float comp4(float4 v, int k) {
    return (k == 0) ? v.x : (k == 1) ? v.y : (k == 2) ? v.z : v.w;
}

// ---------------------------------------------------------------------------
// Main kernel: each thread computes a 4-row x 16-col output tile.
// 256 threads/block -> 256 rows per block, lanes split cols 4 ways (cg).
// Weight LDS amortized over 4 rows; x loaded float4 from global.
// ---------------------------------------------------------------------------
__global__ __launch_bounds__(256) void pnn_main_kernel(
    const float* __restrict__ embeds,   // [N, 64]
    const float* __restrict__ dists,    // [N, 32]
    const float* __restrict__ W,        // [128, 64]
    const float* __restrict__ bias,     // [64]
    float* __restrict__ out,            // [N, 64]
    int N)
{
    __shared__ float sW[ET * DN];   // rows 0..31 = P', rows 32..95 = W2
    __shared__ float sB[DN];

    int tid = threadIdx.x;
    for (int i = tid; i < AN * DN; i += 256) sW[i] = g_P[i];
    for (int i = tid; i < DN * DN; i += 256) sW[AN * DN + i] = W[DN * DN + i];
    if (tid < DN) sB[tid] = bias[tid];
    __syncthreads();

    int cg = tid & 3;          // col group: cols [cg*16, cg*16+16)
    int rg = tid >> 2;         // row group within block
    int rbase = blockIdx.x * 256 + rg * 4;

    int rr[4];
#pragma unroll
    for (int r = 0; r < 4; r++) {
        int row = rbase + r;
        rr[r] = (row < N) ? row : (N - 1);   // clamp loads; stores guarded
    }

    // 4 rows x 8 packed (16 cols) accumulators, init to bias
    unsigned long long acc[4][8];
    {
        const float2* b2 = (const float2*)(sB + cg * 16);
#pragma unroll
        for (int j = 0; j < 8; j++) {
            float2 bv = b2[j];
            unsigned long long p;
            asm("mov.b64 %0, {%1, %2};" : "=l"(p) : "f"(bv.x), "f"(bv.y));
#pragma unroll
            for (int r = 0; r < 4; r++) acc[r][j] = p;
        }
    }

    const float* swc = sW + cg * 16;   // this thread's col slice base

    // ---- Part 1: K = 0..31 (dists) ----
#pragma unroll 2
    for (int g = 0; g < AN / 4; g++) {
        float4 x4[4];
#pragma unroll
        for (int r = 0; r < 4; r++)
            x4[r] = ((const float4*)(dists + (size_t)rr[r] * AN))[g];
#pragma unroll
        for (int k = 0; k < 4; k++) {
            int e = g * 4 + k;
            const ulonglong2* wrow = (const ulonglong2*)(swc + e * DN);
            ulonglong2 w0 = wrow[0];
            ulonglong2 w1 = wrow[1];
            unsigned long long x2[4];
#pragma unroll
            for (int r = 0; r < 4; r++) x2[r] = pack2(comp4(x4[r], k));
#pragma unroll
            for (int r = 0; r < 4; r++) {
                ffma2(acc[r][0], x2[r], w0.x);
                ffma2(acc[r][1], x2[r], w0.y);
                ffma2(acc[r][2], x2[r], w1.x);
                ffma2(acc[r][3], x2[r], w1.y);
            }
            const ulonglong2* wrow2 = (const ulonglong2*)(swc + e * DN + 8);
            ulonglong2 w2 = wrow2[0];
            ulonglong2 w3 = wrow2[1];
#pragma unroll
            for (int r = 0; r < 4; r++) {
                ffma2(acc[r][4], x2[r], w2.x);
                ffma2(acc[r][5], x2[r], w2.y);
                ffma2(acc[r][6], x2[r], w3.x);
                ffma2(acc[r][7], x2[r], w3.y);
            }
        }
    }

    // ---- Part 2: K = 32..95 (embeds) ----
#pragma unroll 2
    for (int g = 0; g < DN / 4; g++) {
        float4 x4[4];
#pragma unroll
        for (int r = 0; r < 4; r++)
            x4[r] = ((const float4*)(embeds + (size_t)rr[r] * DN))[g];
#pragma unroll
        for (int k = 0; k < 4; k++) {
            int e = AN + g * 4 + k;
            const ulonglong2* wrow = (const ulonglong2*)(swc + e * DN);
            ulonglong2 w0 = wrow[0];
            ulonglong2 w1 = wrow[1];
            unsigned long long x2[4];
#pragma unroll
            for (int r = 0; r < 4; r++) x2[r] = pack2(comp4(x4[r], k));
#pragma unroll
            for (int r = 0; r < 4; r++) {
                ffma2(acc[r][0], x2[r], w0.x);
                ffma2(acc[r][1], x2[r], w0.y);
                ffma2(acc[r][2], x2[r], w1.x);
                ffma2(acc[r][3], x2[r], w1.y);
            }
            const ulonglong2* wrow2 = (const ulonglong2*)(swc + e * DN + 8);
            ulonglong2 w2 = wrow2[0];
            ulonglong2 w3 = wrow2[1];
#pragma unroll
            for (int r = 0; r < 4; r++) {
                ffma2(acc[r][4], x2[r], w2.x);
                ffma2(acc[r][5], x2[r], w2.y);
                ffma2(acc[r][6], x2[r], w3.x);
                ffma2(acc[r][7], x2[r], w3.y);
            }
        }
    }

    // ---- Store: 4 rows x 16 cols ----
#pragma unroll
    for (int r = 0; r < 4; r++) {
        int row = rbase + r;
        if (row < N) {
            float4* orow = (float4*)(out + (size_t)row * DN + cg * 16);
#pragma unroll
            for (int j = 0; j < 4; j++) {
                float2 a0 = *(float2*)&acc[r][2 * j + 0];
                float2 a1 = *(float2*)&acc[r][2 * j + 1];
                orow[j] = make_float4(a0.x, a0.y, a1.x, a1.y);
            }
        }
    }
}

extern "C" void kernel_launch(void* const* d_in, const int* in_sizes, int n_in,
                              void* d_out, int out_size) {
    const float* embeds  = (const float*)d_in[0];
    const float* dists   = (const float*)d_in[1];
    const float* W       = (const float*)d_in[2];
    const float* bias    = (const float*)d_in[3];
    const int*   anchors = (const int*)  d_in[4];

    int N = in_sizes[0] / DN;   // 100000

    precompute_P_kernel<<<(AN * DN + 255) / 256, 256>>>(embeds, W, anchors);

    int rows_per_block = 256;
    int blocks = (N + rows_per_block - 1) / rows_per_block;
    pnn_main_kernel<<<blocks, 256>>>(embeds, dists, W, bias,
                                     (float*)d_out, N);
}

// round 3
// speedup vs baseline: 1.5894x; 1.5894x over previous
#include <cuda_runtime.h>

#define DN 64     // EMB_DIM
#define AN 32     // N_ANCHORS
#define ET 96     // AN + DN combined K
#define ROWS_PB 128
#define XSTRIDE 132   // padded row length of transposed x tile (16B-aligned, conflict-free)

// Precomputed P' = (1/A) * set_emb @ W1  [32 x 64]
__device__ float g_P[AN * DN];

__global__ void precompute_P_kernel(const float* __restrict__ embeds,
                                    const float* __restrict__ W,
                                    const int*   __restrict__ anchorset_id) {
    int idx = blockIdx.x * blockDim.x + threadIdx.x;
    if (idx >= AN * DN) return;
    int a = idx >> 6;
    int d = idx & 63;
    long row = (long)anchorset_id[a];
    const float* erow = embeds + row * DN;
    float s = 0.0f;
#pragma unroll
    for (int e = 0; e < DN; e++) s = fmaf(erow[e], W[e * DN + d], s);
    g_P[idx] = s * (1.0f / (float)AN);
}

__device__ __forceinline__ unsigned long long pack2(float x) {
    unsigned long long r;
    asm("mov.b64 %0, {%1, %1};" : "=l"(r) : "f"(x));
    return r;
}
__device__ __forceinline__ void ffma2(unsigned long long& a,
                                      unsigned long long x,
                                      unsigned long long w) {
    asm("fma.rn.f32x2 %0, %1, %2, %0;" : "+l"(a) : "l"(x), "l"(w));
}

// ---------------------------------------------------------------------------
// Block: 128 rows x 64 cols. Thread: 4 rows x 8 cols.
// x tile transposed into smem [96][132]; W [96][64]; all LDS conflict-free.
// ---------------------------------------------------------------------------
__global__ __launch_bounds__(256, 3) void pnn_main_kernel(
    const float* __restrict__ embeds,   // [N, 64]
    const float* __restrict__ dists,    // [N, 32]
    const float* __restrict__ W,        // [128, 64]
    const float* __restrict__ bias,     // [64]
    float* __restrict__ out,            // [N, 64]
    int N)
{
    extern __shared__ float smem[];
    float* sX = smem;                      // [ET][XSTRIDE]
    float* sW = smem + ET * XSTRIDE;       // [ET][DN]
    float* sB = sW + ET * DN;              // [DN]

    int tid = threadIdx.x;
    int rb = blockIdx.x * ROWS_PB;

    // ---- stage weights ----
    for (int i = tid; i < AN * DN; i += 256) sW[i] = g_P[i];
    for (int i = tid; i < DN * DN; i += 256) sW[AN * DN + i] = W[DN * DN + i];
    if (tid < DN) sB[tid] = bias[tid];

    // ---- stage x transposed: dists part (e = 0..31) ----
    // 128 rows x 8 float4 per row = 1024 float4, coalesced LDG
#pragma unroll
    for (int it = 0; it < 4; it++) {
        int i = tid + it * 256;            // 0..1023
        int r = i >> 3;
        int c4 = i & 7;
        int row = rb + r; if (row >= N) row = N - 1;
        float4 v = ((const float4*)(dists + (size_t)row * AN))[c4];
        int e = c4 * 4;
        sX[(e + 0) * XSTRIDE + r] = v.x;
        sX[(e + 1) * XSTRIDE + r] = v.y;
        sX[(e + 2) * XSTRIDE + r] = v.z;
        sX[(e + 3) * XSTRIDE + r] = v.w;
    }
    // ---- stage x transposed: embeds part (e = 32..95) ----
#pragma unroll
    for (int it = 0; it < 8; it++) {
        int i = tid + it * 256;            // 0..2047
        int r = i >> 4;
        int c4 = i & 15;
        int row = rb + r; if (row >= N) row = N - 1;
        float4 v = ((const float4*)(embeds + (size_t)row * DN))[c4];
        int e = AN + c4 * 4;
        sX[(e + 0) * XSTRIDE + r] = v.x;
        sX[(e + 1) * XSTRIDE + r] = v.y;
        sX[(e + 2) * XSTRIDE + r] = v.z;
        sX[(e + 3) * XSTRIDE + r] = v.w;
    }
    __syncthreads();

    // ---- thread tile coordinates ----
    int lane = tid & 31;
    int warp = tid >> 5;
    int r0 = warp * 16 + (lane >> 3) * 4;   // 4 rows: r0..r0+3
    int c0 = (lane & 7) * 8;                // 8 cols: c0..c0+7

    // ---- init accumulators to bias ----
    unsigned long long acc[4][4];
    {
        const float2* b2 = (const float2*)(sB + c0);
#pragma unroll
        for (int j = 0; j < 4; j++) {
            float2 bv = b2[j];
            unsigned long long p;
            asm("mov.b64 %0, {%1, %2};" : "=l"(p) : "f"(bv.x), "f"(bv.y));
#pragma unroll
            for (int r = 0; r < 4; r++) acc[r][j] = p;
        }
    }

    const float* xbase = sX + r0;
    const float* wbase = sW + c0;

    // ---- main K loop: 1 LDS.128 (x) + 2 LDS.128 (W) -> 16 FFMA2 ----
#pragma unroll 4
    for (int e = 0; e < ET; e++) {
        float4 xv = *(const float4*)(xbase + e * XSTRIDE);
        const ulonglong2* wp = (const ulonglong2*)(wbase + e * DN);
        ulonglong2 wa = wp[0];
        ulonglong2 wb = wp[1];

        unsigned long long x0 = pack2(xv.x);
        unsigned long long x1 = pack2(xv.y);
        unsigned long long x2 = pack2(xv.z);
        unsigned long long x3 = pack2(xv.w);

        ffma2(acc[0][0], x0, wa.x); ffma2(acc[0][1], x0, wa.y);
        ffma2(acc[0][2], x0, wb.x); ffma2(acc[0][3], x0, wb.y);
        ffma2(acc[1][0], x1, wa.x); ffma2(acc[1][1], x1, wa.y);
        ffma2(acc[1][2], x1, wb.x); ffma2(acc[1][3], x1, wb.y);
        ffma2(acc[2][0], x2, wa.x); ffma2(acc[2][1], x2, wa.y);
        ffma2(acc[2][2], x2, wb.x); ffma2(acc[2][3], x2, wb.y);
        ffma2(acc[3][0], x3, wa.x); ffma2(acc[3][1], x3, wa.y);
        ffma2(acc[3][2], x3, wb.x); ffma2(acc[3][3], x3, wb.y);
    }

    // ---- store 4 rows x 8 cols ----
#pragma unroll
    for (int r = 0; r < 4; r++) {
        int row = rb + r0 + r;
        if (row < N) {
            float4* op = (float4*)(out + (size_t)row * DN + c0);
            float2 a0 = *(float2*)&acc[r][0];
            float2 a1 = *(float2*)&acc[r][1];
            float2 a2 = *(float2*)&acc[r][2];
            float2 a3 = *(float2*)&acc[r][3];
            op[0] = make_float4(a0.x, a0.y, a1.x, a1.y);
            op[1] = make_float4(a2.x, a2.y, a3.x, a3.y);
        }
    }
}

extern "C" void kernel_launch(void* const* d_in, const int* in_sizes, int n_in,
                              void* d_out, int out_size) {
    const float* embeds  = (const float*)d_in[0];
    const float* dists   = (const float*)d_in[1];
    const float* W       = (const float*)d_in[2];
    const float* bias    = (const float*)d_in[3];
    const int*   anchors = (const int*)  d_in[4];

    int N = in_sizes[0] / DN;   // 100000

    precompute_P_kernel<<<(AN * DN + 255) / 256, 256>>>(embeds, W, anchors);

    size_t smem_bytes = (size_t)(ET * XSTRIDE + ET * DN + DN) * sizeof(float);
    cudaFuncSetAttribute(pnn_main_kernel,
                         cudaFuncAttributeMaxDynamicSharedMemorySize,
                         (int)smem_bytes);

    int blocks = (N + ROWS_PB - 1) / ROWS_PB;
    pnn_main_kernel<<<blocks, 256, smem_bytes>>>(embeds, dists, W, bias,
                                                 (float*)d_out, N);
}

// round 5
// speedup vs baseline: 3.3391x; 2.1008x over previous
#include <cuda_runtime.h>
#include <cuda_bf16.h>
#include <mma.h>
#include <cstdint>

using namespace nvcuda;

#define DN 64       // EMB_DIM / GEMM N
#define AN 32       // N_ANCHORS
#define KP 96       // fp32 K (32 dists + 64 embeds)
#define LD 104      // padded smem K stride (elems), 16B-aligned rows
#define ROWS_PB 128

// SMEM byte offsets
#define SM_XHI  0
#define SM_XLO  26624
#define SM_WHI  53248
#define SM_WLO  66560
#define SM_BIAS 79872
#define SM_TOTAL 80128

__device__ float g_P[AN * DN];                 // P' = (1/A) set_emb @ W1
__device__ __nv_bfloat16 g_Whi[DN * KP];       // W' hi, [d][k]
__device__ __nv_bfloat16 g_Wlo[DN * KP];       // W' lo, [d][k]

// ---------------------------------------------------------------------------
__global__ void precompute_P_kernel(const float* __restrict__ embeds,
                                    const float* __restrict__ W,
                                    const int*   __restrict__ anchorset_id) {
    int idx = blockIdx.x * blockDim.x + threadIdx.x;
    if (idx >= AN * DN) return;
    int a = idx >> 6;
    int d = idx & 63;
    long row = (long)anchorset_id[a];
    const float* erow = embeds + row * DN;
    float s = 0.0f;
#pragma unroll
    for (int e = 0; e < DN; e++) s = fmaf(erow[e], W[e * DN + d], s);
    g_P[idx] = s * (1.0f / (float)AN);
}

// Build W' hi/lo: w[k,d] = P'[k][d] (k<32) else W[(32+k)*64+d]
__global__ void build_W_kernel(const float* __restrict__ W) {
    int idx = blockIdx.x * blockDim.x + threadIdx.x;
    if (idx >= DN * KP) return;
    int d = idx / KP;
    int k = idx % KP;
    float w = (k < AN) ? g_P[k * DN + d] : W[(AN + k) * DN + d];
    __nv_bfloat16 hi = __float2bfloat16_rn(w);
    __nv_bfloat16 lo = __float2bfloat16_rn(w - __bfloat162float(hi));
    g_Whi[d * KP + k] = hi;
    g_Wlo[d * KP + k] = lo;
}

// ---------------------------------------------------------------------------
__device__ __forceinline__ void split2(float a, float b, uint32_t& hi, uint32_t& lo) {
    __nv_bfloat162 h = __floats2bfloat162_rn(a, b);
    float ra = a - __bfloat162float(h.x);
    float rb = b - __bfloat162float(h.y);
    __nv_bfloat162 l = __floats2bfloat162_rn(ra, rb);
    hi = *(uint32_t*)&h;
    lo = *(uint32_t*)&l;
}

// ---------------------------------------------------------------------------
// Main kernel: 128 rows/CTA, 8 warps x (16 rows x 64 cols), WMMA bf16 split.
// ---------------------------------------------------------------------------
__global__ __launch_bounds__(256, 2) void pnn_wmma_kernel(
    const float* __restrict__ embeds,   // [N, 64]
    const float* __restrict__ dists,    // [N, 32]
    const float* __restrict__ bias,     // [64]
    float* __restrict__ out,            // [N, 64]
    int N)
{
    extern __shared__ char smem[];
    __nv_bfloat16* sXhi = (__nv_bfloat16*)(smem + SM_XHI);   // [128][LD]
    __nv_bfloat16* sXlo = (__nv_bfloat16*)(smem + SM_XLO);   // [128][LD]
    __nv_bfloat16* sWhi = (__nv_bfloat16*)(smem + SM_WHI);   // col-major [64][LD]
    __nv_bfloat16* sWlo = (__nv_bfloat16*)(smem + SM_WLO);
    float*         sB   = (float*)(smem + SM_BIAS);

    int tid = threadIdx.x;
    int rb = blockIdx.x * ROWS_PB;

    // ---- stage x: dists (k 0..31), 128 rows x 8 float4 ----
#pragma unroll
    for (int it = 0; it < 4; it++) {
        int i = tid + it * 256;
        int r = i >> 3, c4 = i & 7;
        int row = rb + r; if (row >= N) row = N - 1;
        float4 v = ((const float4*)(dists + (size_t)row * AN))[c4];
        int k0 = c4 * 4;
        uint32_t h0, l0, h1, l1;
        split2(v.x, v.y, h0, l0);
        split2(v.z, v.w, h1, l1);
        *(uint2*)(sXhi + r * LD + k0) = make_uint2(h0, h1);
        *(uint2*)(sXlo + r * LD + k0) = make_uint2(l0, l1);
    }
    // ---- stage x: embeds (k 32..95), 128 rows x 16 float4 ----
#pragma unroll
    for (int it = 0; it < 8; it++) {
        int i = tid + it * 256;
        int r = i >> 4, c4 = i & 15;
        int row = rb + r; if (row >= N) row = N - 1;
        float4 v = ((const float4*)(embeds + (size_t)row * DN))[c4];
        int k0 = AN + c4 * 4;
        uint32_t h0, l0, h1, l1;
        split2(v.x, v.y, h0, l0);
        split2(v.z, v.w, h1, l1);
        *(uint2*)(sXhi + r * LD + k0) = make_uint2(h0, h1);
        *(uint2*)(sXlo + r * LD + k0) = make_uint2(l0, l1);
    }
    // ---- stage W hi/lo, col-major [d][k] -> sW[d*LD + k], 8 elems/chunk ----
#pragma unroll
    for (int it = 0; it < 3; it++) {
        int i = tid + it * 256;   // 0..767
        int d = i / 12, kc = i % 12;
        *(uint4*)(sWhi + d * LD + kc * 8) = *(const uint4*)(g_Whi + d * KP + kc * 8);
        *(uint4*)(sWlo + d * LD + kc * 8) = *(const uint4*)(g_Wlo + d * KP + kc * 8);
    }
    if (tid < DN) sB[tid] = bias[tid];
    __syncthreads();

    // ---- WMMA ----
    int wid = tid >> 5;
    int r0 = wid * 16;                      // warp's 16 rows within tile

    wmma::fragment<wmma::accumulator, 16, 16, 16, float> acc[4];
#pragma unroll
    for (int t = 0; t < 4; t++) wmma::fill_fragment(acc[t], 0.0f);

    // passes 1+2 fused (share b_hi): acc += a_hi*b_hi + a_lo*b_hi
#pragma unroll
    for (int ks = 0; ks < KP / 16; ks++) {
        int k0 = ks * 16;
        wmma::fragment<wmma::matrix_a, 16, 16, 16, __nv_bfloat16, wmma::row_major> ah, al;
        wmma::load_matrix_sync(ah, sXhi + r0 * LD + k0, LD);
        wmma::load_matrix_sync(al, sXlo + r0 * LD + k0, LD);
#pragma unroll
        for (int t = 0; t < 4; t++) {
            wmma::fragment<wmma::matrix_b, 16, 16, 16, __nv_bfloat16, wmma::col_major> bh;
            wmma::load_matrix_sync(bh, sWhi + (t * 16) * LD + k0, LD);
            wmma::mma_sync(acc[t], ah, bh, acc[t]);
            wmma::mma_sync(acc[t], al, bh, acc[t]);
        }
    }
    // pass 3: acc += a_hi*b_lo
#pragma unroll
    for (int ks = 0; ks < KP / 16; ks++) {
        int k0 = ks * 16;
        wmma::fragment<wmma::matrix_a, 16, 16, 16, __nv_bfloat16, wmma::row_major> ah;
        wmma::load_matrix_sync(ah, sXhi + r0 * LD + k0, LD);
#pragma unroll
        for (int t = 0; t < 4; t++) {
            wmma::fragment<wmma::matrix_b, 16, 16, 16, __nv_bfloat16, wmma::col_major> bl;
            wmma::load_matrix_sync(bl, sWlo + (t * 16) * LD + k0, LD);
            wmma::mma_sync(acc[t], ah, bl, acc[t]);
        }
    }

    // ---- epilogue: dump frags to smem overlay, add bias, STG ----
    __syncthreads();   // x/W tiles dead; safe to overlay
    float* epi = (float*)smem;               // [128][64] overlay
    float* wepi = epi + r0 * DN;             // this warp's 16x64 region
#pragma unroll
    for (int t = 0; t < 4; t++)
        wmma::store_matrix_sync(wepi + t * 16, acc[t], DN, wmma::mem_row_major);
    __syncwarp();

    int lane = tid & 31;
#pragma unroll
    for (int q = 0; q < 8; q++) {
        int f4 = lane + q * 32;              // 0..255: 16 rows x 16 float4
        int r = f4 >> 4, c4 = f4 & 15;
        int row = rb + r0 + r;
        if (row < N) {
            float4 v = ((const float4*)(wepi + r * DN))[c4];
            float4 b4 = ((const float4*)sB)[c4];
            v.x += b4.x; v.y += b4.y; v.z += b4.z; v.w += b4.w;
            ((float4*)(out + (size_t)row * DN))[c4] = v;
        }
    }
}

// ---------------------------------------------------------------------------
extern "C" void kernel_launch(void* const* d_in, const int* in_sizes, int n_in,
                              void* d_out, int out_size) {
    const float* embeds  = (const float*)d_in[0];
    const float* dists   = (const float*)d_in[1];
    const float* W       = (const float*)d_in[2];
    const float* bias    = (const float*)d_in[3];
    const int*   anchors = (const int*)  d_in[4];

    int N = in_sizes[0] / DN;   // 100000

    precompute_P_kernel<<<(AN * DN + 255) / 256, 256>>>(embeds, W, anchors);
    build_W_kernel<<<(DN * KP + 255) / 256, 256>>>(W);

    cudaFuncSetAttribute(pnn_wmma_kernel,
                         cudaFuncAttributeMaxDynamicSharedMemorySize, SM_TOTAL);
    int blocks = (N + ROWS_PB - 1) / ROWS_PB;
    pnn_wmma_kernel<<<blocks, 256, SM_TOTAL>>>(embeds, dists, bias,
                                               (float*)d_out, N);
}